// round 9
// baseline (speedup 1.0000x reference)
#include <cuda_runtime.h>
#include <math.h>

#define B_   2
#define T_   2048
#define DIM_ 1024
#define H_   16
#define HD_  64
#define G_   4
#define KVD_ 256          // (H_/G_) * HD_
#define ROWS_ (B_*T_)     // 4096

// ---------------- scratch (no cudaMalloc allowed) ----------------
__device__ float g_q  [ROWS_*DIM_];
__device__ float g_k  [ROWS_*KVD_];
__device__ float g_v  [ROWS_*KVD_];
__device__ float g_qr [ROWS_*DIM_];
__device__ float g_kr [ROWS_*KVD_];
__device__ float g_ctx[ROWS_*DIM_];

// ---------------- SGEMM: Y = X @ W^T + bias ----------------
// X[M,K] row-major, W[N,K] row-major, Y[M,N]. M%64==0, N%64==0, K%16==0.
__global__ __launch_bounds__(256) void sgemm_bias_kernel(
    const float* __restrict__ X, const float* __restrict__ W,
    const float* __restrict__ bias, float* __restrict__ Y,
    int M, int N, int K)
{
    __shared__ float Xs[64][17];
    __shared__ float Ws[64][17];

    int tid = threadIdx.x;
    int tx = tid & 15, ty = tid >> 4;
    int row0 = blockIdx.y << 6;
    int col0 = blockIdx.x << 6;

    int lr = tid >> 2;          // 0..63
    int lk = (tid & 3) << 2;    // 0,4,8,12

    const float* Xp = X + (size_t)(row0 + lr) * K + lk;
    const float* Wp = W + (size_t)(col0 + lr) * K + lk;

    float acc[4][4] = {};

    for (int k0 = 0; k0 < K; k0 += 16) {
        float4 xv = *reinterpret_cast<const float4*>(Xp + k0);
        float4 wv = *reinterpret_cast<const float4*>(Wp + k0);
        Xs[lr][lk+0]=xv.x; Xs[lr][lk+1]=xv.y; Xs[lr][lk+2]=xv.z; Xs[lr][lk+3]=xv.w;
        Ws[lr][lk+0]=wv.x; Ws[lr][lk+1]=wv.y; Ws[lr][lk+2]=wv.z; Ws[lr][lk+3]=wv.w;
        __syncthreads();
        #pragma unroll
        for (int kk = 0; kk < 16; kk++) {
            float a[4], b[4];
            #pragma unroll
            for (int i = 0; i < 4; i++) a[i] = Xs[(ty<<2)+i][kk];
            #pragma unroll
            for (int j = 0; j < 4; j++) b[j] = Ws[(tx<<2)+j][kk];
            #pragma unroll
            for (int i = 0; i < 4; i++)
                #pragma unroll
                for (int j = 0; j < 4; j++)
                    acc[i][j] = fmaf(a[i], b[j], acc[i][j]);
        }
        __syncthreads();
    }

    #pragma unroll
    for (int i = 0; i < 4; i++) {
        int r = row0 + (ty<<2) + i;
        #pragma unroll
        for (int j = 0; j < 4; j++) {
            int c = col0 + (tx<<2) + j;
            Y[(size_t)r * N + c] = acc[i][j] + bias[c];
        }
    }
}

// ---------------- RoPE ----------------
// out[d] = x[d]*cos(t*f_j) + rot[d]*sin(t*f_j); j = d%32, f_j = 10000^{-j/32}
// rot[d] = -x[2d+1] (d<32) ; rot[d] = x[2(d-32)] (d>=32), within each 64-wide head.
__global__ __launch_bounds__(256) void rope_kernel(
    const float* __restrict__ in, float* __restrict__ out,
    int width, int total)
{
    int idx = blockIdx.x * blockDim.x + threadIdx.x;
    if (idx >= total) return;
    int d   = idx & 63;
    int row = idx / width;          // b*T + t  (width is a power of two)
    int t   = row & (T_ - 1);
    int j   = d & 31;

    float inv = (float)pow(10000.0, -(double)j * 0.03125);  // 10000^{-j/32}
    float ang = (float)t * inv;
    float s, c;
    sincosf(ang, &s, &c);

    int hb = idx - d;
    float x = in[idx];
    float r = (d < 32) ? -in[hb + 2*d + 1] : in[hb + 2*(d - 32)];
    out[idx] = x * c + r * s;
}

// ---------------- Flash attention (fp32, full softmax) ----------------
// grid: (T/64 query tiles, B*H). block: 256 threads (16x16), 4x4 microtile.
// dynamic smem: Qs[64][68] | Ks[64][68] (reused for P) | Vs[64][68]
// stride 68 floats = 272 B keeps &Vs[j*P + 4*tx] 16B-aligned -> LDS.128 in PV.
__global__ __launch_bounds__(256) void attn_kernel(
    const float* __restrict__ Q, const float* __restrict__ K,
    const float* __restrict__ V, float* __restrict__ ctx)
{
    extern __shared__ float sm[];
    const int P = 68;
    float* Qs = sm;
    float* Ks = sm + 64 * P;
    float* Vs = sm + 2 * 64 * P;

    int tid = threadIdx.x;
    int tx = tid & 15, ty = tid >> 4;
    int qt = blockIdx.x;
    int bh = blockIdx.y;
    int b = bh >> 4, h = bh & 15, kvh = h >> 2;
    int t0 = qt << 6;

    int lrow = tid >> 4;            // 0..15
    int lc   = (tid & 15) << 2;     // 0..60

    const float scale = 0.125f;     // 1/sqrt(64)

    // load Q tile (scale folded in)
    #pragma unroll
    for (int it = 0; it < 4; it++) {
        int r = (it << 4) + lrow;
        float4 q4 = *reinterpret_cast<const float4*>(
            &Q[(size_t)(b*T_ + t0 + r) * DIM_ + h*HD_ + lc]);
        Qs[r*P + lc+0] = q4.x * scale;
        Qs[r*P + lc+1] = q4.y * scale;
        Qs[r*P + lc+2] = q4.z * scale;
        Qs[r*P + lc+3] = q4.w * scale;
    }

    float m[4], l[4], o[4][4];
    #pragma unroll
    for (int i = 0; i < 4; i++) {
        m[i] = -INFINITY; l[i] = 0.f;
        #pragma unroll
        for (int k = 0; k < 4; k++) o[i][k] = 0.f;
    }

    for (int kt = 0; kt < T_/64; kt++) {
        int s0 = kt << 6;
        __syncthreads();   // previous PV done with Ks(P)/Vs; also orders first-iter Q writes
        #pragma unroll
        for (int it = 0; it < 4; it++) {
            int r = (it << 4) + lrow;
            size_t base = (size_t)(b*T_ + s0 + r) * KVD_ + kvh*HD_ + lc;
            float4 k4 = *reinterpret_cast<const float4*>(&K[base]);
            float4 v4 = *reinterpret_cast<const float4*>(&V[base]);
            Ks[r*P + lc+0] = k4.x; Ks[r*P + lc+1] = k4.y;
            Ks[r*P + lc+2] = k4.z; Ks[r*P + lc+3] = k4.w;
            *reinterpret_cast<float4*>(&Vs[r*P + lc]) = v4;
        }
        __syncthreads();

        // S = (Q*scale) @ K^T  (4x4 per thread)
        float s_[4][4] = {};
        #pragma unroll 8
        for (int kk = 0; kk < HD_; kk++) {
            float a[4], bb[4];
            #pragma unroll
            for (int i = 0; i < 4; i++) a[i]  = Qs[((ty<<2)+i)*P + kk];
            #pragma unroll
            for (int j = 0; j < 4; j++) bb[j] = Ks[((tx<<2)+j)*P + kk];
            #pragma unroll
            for (int i = 0; i < 4; i++)
                #pragma unroll
                for (int j = 0; j < 4; j++)
                    s_[i][j] = fmaf(a[i], bb[j], s_[i][j]);
        }

        // online softmax update (rows shared by 16 lanes with the same ty)
        #pragma unroll
        for (int i = 0; i < 4; i++) {
            float mt = fmaxf(fmaxf(s_[i][0], s_[i][1]), fmaxf(s_[i][2], s_[i][3]));
            mt = fmaxf(mt, __shfl_xor_sync(0xffffffffu, mt, 1));
            mt = fmaxf(mt, __shfl_xor_sync(0xffffffffu, mt, 2));
            mt = fmaxf(mt, __shfl_xor_sync(0xffffffffu, mt, 4));
            mt = fmaxf(mt, __shfl_xor_sync(0xffffffffu, mt, 8));
            float mn = fmaxf(m[i], mt);
            float al = __expf(m[i] - mn);
            m[i] = mn;
            float rs = 0.f;
            #pragma unroll
            for (int j = 0; j < 4; j++) {
                float p = __expf(s_[i][j] - mn);
                s_[i][j] = p;
                rs += p;
            }
            rs += __shfl_xor_sync(0xffffffffu, rs, 1);
            rs += __shfl_xor_sync(0xffffffffu, rs, 2);
            rs += __shfl_xor_sync(0xffffffffu, rs, 4);
            rs += __shfl_xor_sync(0xffffffffu, rs, 8);
            l[i] = l[i] * al + rs;
            #pragma unroll
            for (int k = 0; k < 4; k++) o[i][k] *= al;
        }

        __syncthreads();   // everyone done reading Ks — reuse it for P
        #pragma unroll
        for (int i = 0; i < 4; i++)
            #pragma unroll
            for (int j = 0; j < 4; j++)
                Ks[((ty<<2)+i)*P + (tx<<2)+j] = s_[i][j];
        __syncthreads();

        // O += P @ V   (vv reads are 16B-aligned float4 -> LDS.128)
        #pragma unroll 8
        for (int j = 0; j < 64; j++) {
            float p[4];
            #pragma unroll
            for (int i = 0; i < 4; i++) p[i]  = Ks[((ty<<2)+i)*P + j];
            float4 vv = *reinterpret_cast<const float4*>(&Vs[j*P + (tx<<2)]);
            #pragma unroll
            for (int i = 0; i < 4; i++) {
                o[i][0] = fmaf(p[i], vv.x, o[i][0]);
                o[i][1] = fmaf(p[i], vv.y, o[i][1]);
                o[i][2] = fmaf(p[i], vv.z, o[i][2]);
                o[i][3] = fmaf(p[i], vv.w, o[i][3]);
            }
        }
    }

    // epilogue: normalize and write context in [b, t, H*HD] layout
    #pragma unroll
    for (int i = 0; i < 4; i++) {
        float rinv = 1.0f / l[i];
        int t = t0 + (ty<<2) + i;
        #pragma unroll
        for (int k = 0; k < 4; k++)
            ctx[(size_t)(b*T_ + t) * DIM_ + h*HD_ + (tx<<2)+k] = o[i][k] * rinv;
    }
}

// ---------------- launch ----------------
extern "C" void kernel_launch(void* const* d_in, const int* in_sizes, int n_in,
                              void* d_out, int out_size) {
    const float* hs = (const float*)d_in[0];
    const float* Wq = (const float*)d_in[1];
    const float* bq = (const float*)d_in[2];
    const float* Wk = (const float*)d_in[3];
    const float* bk = (const float*)d_in[4];
    const float* Wv = (const float*)d_in[5];
    const float* bv = (const float*)d_in[6];
    const float* Wo = (const float*)d_in[7];
    const float* bo = (const float*)d_in[8];
    float* out = (float*)d_out;

    float *q, *k, *v, *qr, *kr, *ctx;
    cudaGetSymbolAddress((void**)&q,   g_q);
    cudaGetSymbolAddress((void**)&k,   g_k);
    cudaGetSymbolAddress((void**)&v,   g_v);
    cudaGetSymbolAddress((void**)&qr,  g_qr);
    cudaGetSymbolAddress((void**)&kr,  g_kr);
    cudaGetSymbolAddress((void**)&ctx, g_ctx);

    // QKV projections
    sgemm_bias_kernel<<<dim3(DIM_/64, ROWS_/64), 256>>>(hs, Wq, bq, q, ROWS_, DIM_, DIM_);
    sgemm_bias_kernel<<<dim3(KVD_/64, ROWS_/64), 256>>>(hs, Wk, bk, k, ROWS_, KVD_, DIM_);
    sgemm_bias_kernel<<<dim3(KVD_/64, ROWS_/64), 256>>>(hs, Wv, bv, v, ROWS_, KVD_, DIM_);

    // RoPE on Q and K
    rope_kernel<<<(ROWS_*DIM_ + 255)/256, 256>>>(q, qr, DIM_, ROWS_*DIM_);
    rope_kernel<<<(ROWS_*KVD_ + 255)/256, 256>>>(k, kr, KVD_, ROWS_*KVD_);

    // attention
    int smem = 3 * 64 * 68 * (int)sizeof(float);   // 52224 B
    cudaFuncSetAttribute(attn_kernel, cudaFuncAttributeMaxDynamicSharedMemorySize, smem);
    attn_kernel<<<dim3(T_/64, B_*H_), 256, smem>>>(qr, kr, v, ctx);

    // output projection
    sgemm_bias_kernel<<<dim3(DIM_/64, ROWS_/64), 256>>>(ctx, Wo, bo, out, ROWS_, DIM_, DIM_);
}

// round 12
// speedup vs baseline: 1.3475x; 1.3475x over previous
#include <cuda_runtime.h>
#include <math.h>

#define B_   2
#define T_   2048
#define DIM_ 1024
#define H_   16
#define HD_  64
#define G_   4
#define KVD_ 256          // (H_/G_) * HD_
#define ROWS_ (B_*T_)     // 4096

// ---------------- scratch (no cudaMalloc allowed) ----------------
__device__ float g_q  [ROWS_*DIM_];
__device__ float g_k  [ROWS_*KVD_];
__device__ float g_v  [ROWS_*KVD_];
__device__ float g_qr [ROWS_*DIM_];
__device__ float g_kr [ROWS_*KVD_];
__device__ float g_ctx[ROWS_*DIM_];

// ---------------- SGEMM: Y = X @ W^T + bias ----------------
// X[M,K] row-major, W[N,K] row-major, Y[M,N]. M%64==0, N%64==0, K%16==0.
__global__ __launch_bounds__(256) void sgemm_bias_kernel(
    const float* __restrict__ X, const float* __restrict__ W,
    const float* __restrict__ bias, float* __restrict__ Y,
    int M, int N, int K)
{
    __shared__ float Xs[64][17];
    __shared__ float Ws[64][17];

    int tid = threadIdx.x;
    int tx = tid & 15, ty = tid >> 4;
    int row0 = blockIdx.y << 6;
    int col0 = blockIdx.x << 6;

    int lr = tid >> 2;          // 0..63
    int lk = (tid & 3) << 2;    // 0,4,8,12

    const float* Xp = X + (size_t)(row0 + lr) * K + lk;
    const float* Wp = W + (size_t)(col0 + lr) * K + lk;

    float acc[4][4] = {};

    for (int k0 = 0; k0 < K; k0 += 16) {
        float4 xv = *reinterpret_cast<const float4*>(Xp + k0);
        float4 wv = *reinterpret_cast<const float4*>(Wp + k0);
        Xs[lr][lk+0]=xv.x; Xs[lr][lk+1]=xv.y; Xs[lr][lk+2]=xv.z; Xs[lr][lk+3]=xv.w;
        Ws[lr][lk+0]=wv.x; Ws[lr][lk+1]=wv.y; Ws[lr][lk+2]=wv.z; Ws[lr][lk+3]=wv.w;
        __syncthreads();
        #pragma unroll
        for (int kk = 0; kk < 16; kk++) {
            float a[4], b[4];
            #pragma unroll
            for (int i = 0; i < 4; i++) a[i] = Xs[(ty<<2)+i][kk];
            #pragma unroll
            for (int j = 0; j < 4; j++) b[j] = Ws[(tx<<2)+j][kk];
            #pragma unroll
            for (int i = 0; i < 4; i++)
                #pragma unroll
                for (int j = 0; j < 4; j++)
                    acc[i][j] = fmaf(a[i], b[j], acc[i][j]);
        }
        __syncthreads();
    }

    #pragma unroll
    for (int i = 0; i < 4; i++) {
        int r = row0 + (ty<<2) + i;
        #pragma unroll
        for (int j = 0; j < 4; j++) {
            int c = col0 + (tx<<2) + j;
            Y[(size_t)r * N + c] = acc[i][j] + bias[c];
        }
    }
}

// ---------------- RoPE (fp32 fast path — no FP64 pow) ----------------
// out[d] = x[d]*cos(t*f_j) + rot[d]*sin(t*f_j); j = d%32, f_j = 10000^{-j/32}
// rot[d] = -x[2d+1] (d<32) ; rot[d] = x[2(d-32)] (d>=32), within each 64-wide head.
// inv_freq = exp2f(-j * log2(10000)/32); fp32 rel-err ~1e-7 -> angle err <=2e-4 rad.
__global__ __launch_bounds__(256) void rope_kernel(
    const float* __restrict__ in, float* __restrict__ out,
    int wshift, int total)
{
    int idx = blockIdx.x * blockDim.x + threadIdx.x;
    if (idx >= total) return;
    int d   = idx & 63;
    int row = idx >> wshift;        // b*T + t
    int t   = row & (T_ - 1);
    int j   = d & 31;

    const float neg_l2_over_32 = -0.4152410118609203f;   // -log2(10000)/32
    float inv = exp2f((float)j * neg_l2_over_32);
    float s, c;
    sincosf((float)t * inv, &s, &c);

    int hb = idx - d;
    float x = in[idx];
    float r = (d < 32) ? -in[hb + 2*d + 1] : in[hb + 2*(d - 32)];
    out[idx] = x * c + r * s;
}

// ---------------- Flash attention (fp32, full softmax) ----------------
// grid: (T/64 query tiles, B*H). block: 256 threads (16x16), 4x4 microtile.
// dynamic smem: Qs[64][68] | Ks[64][68] (reused for P) | Vs[64][68]
// stride 68 floats = 272 B keeps &Vs[j*P + 4*tx] 16B-aligned -> LDS.128 in PV.
__global__ __launch_bounds__(256) void attn_kernel(
    const float* __restrict__ Q, const float* __restrict__ K,
    const float* __restrict__ V, float* __restrict__ ctx)
{
    extern __shared__ float sm[];
    const int P = 68;
    float* Qs = sm;
    float* Ks = sm + 64 * P;
    float* Vs = sm + 2 * 64 * P;

    int tid = threadIdx.x;
    int tx = tid & 15, ty = tid >> 4;
    int qt = blockIdx.x;
    int bh = blockIdx.y;
    int b = bh >> 4, h = bh & 15, kvh = h >> 2;
    int t0 = qt << 6;

    int lrow = tid >> 4;            // 0..15
    int lc   = (tid & 15) << 2;     // 0..60

    const float scale = 0.125f;     // 1/sqrt(64)

    // load Q tile (scale folded in)
    #pragma unroll
    for (int it = 0; it < 4; it++) {
        int r = (it << 4) + lrow;
        float4 q4 = *reinterpret_cast<const float4*>(
            &Q[(size_t)(b*T_ + t0 + r) * DIM_ + h*HD_ + lc]);
        Qs[r*P + lc+0] = q4.x * scale;
        Qs[r*P + lc+1] = q4.y * scale;
        Qs[r*P + lc+2] = q4.z * scale;
        Qs[r*P + lc+3] = q4.w * scale;
    }

    float m[4], l[4], o[4][4];
    #pragma unroll
    for (int i = 0; i < 4; i++) {
        m[i] = -INFINITY; l[i] = 0.f;
        #pragma unroll
        for (int k = 0; k < 4; k++) o[i][k] = 0.f;
    }

    for (int kt = 0; kt < T_/64; kt++) {
        int s0 = kt << 6;
        __syncthreads();   // previous PV done with Ks(P)/Vs; also orders first-iter Q writes
        #pragma unroll
        for (int it = 0; it < 4; it++) {
            int r = (it << 4) + lrow;
            size_t base = (size_t)(b*T_ + s0 + r) * KVD_ + kvh*HD_ + lc;
            float4 k4 = *reinterpret_cast<const float4*>(&K[base]);
            float4 v4 = *reinterpret_cast<const float4*>(&V[base]);
            Ks[r*P + lc+0] = k4.x; Ks[r*P + lc+1] = k4.y;
            Ks[r*P + lc+2] = k4.z; Ks[r*P + lc+3] = k4.w;
            *reinterpret_cast<float4*>(&Vs[r*P + lc]) = v4;
        }
        __syncthreads();

        // S = (Q*scale) @ K^T  (4x4 per thread)
        float s_[4][4] = {};
        #pragma unroll 8
        for (int kk = 0; kk < HD_; kk++) {
            float a[4], bb[4];
            #pragma unroll
            for (int i = 0; i < 4; i++) a[i]  = Qs[((ty<<2)+i)*P + kk];
            #pragma unroll
            for (int j = 0; j < 4; j++) bb[j] = Ks[((tx<<2)+j)*P + kk];
            #pragma unroll
            for (int i = 0; i < 4; i++)
                #pragma unroll
                for (int j = 0; j < 4; j++)
                    s_[i][j] = fmaf(a[i], bb[j], s_[i][j]);
        }

        // online softmax update (rows shared by 16 lanes with the same ty)
        #pragma unroll
        for (int i = 0; i < 4; i++) {
            float mt = fmaxf(fmaxf(s_[i][0], s_[i][1]), fmaxf(s_[i][2], s_[i][3]));
            mt = fmaxf(mt, __shfl_xor_sync(0xffffffffu, mt, 1));
            mt = fmaxf(mt, __shfl_xor_sync(0xffffffffu, mt, 2));
            mt = fmaxf(mt, __shfl_xor_sync(0xffffffffu, mt, 4));
            mt = fmaxf(mt, __shfl_xor_sync(0xffffffffu, mt, 8));
            float mn = fmaxf(m[i], mt);
            float al = __expf(m[i] - mn);
            m[i] = mn;
            float rs = 0.f;
            #pragma unroll
            for (int j = 0; j < 4; j++) {
                float p = __expf(s_[i][j] - mn);
                s_[i][j] = p;
                rs += p;
            }
            rs += __shfl_xor_sync(0xffffffffu, rs, 1);
            rs += __shfl_xor_sync(0xffffffffu, rs, 2);
            rs += __shfl_xor_sync(0xffffffffu, rs, 4);
            rs += __shfl_xor_sync(0xffffffffu, rs, 8);
            l[i] = l[i] * al + rs;
            #pragma unroll
            for (int k = 0; k < 4; k++) o[i][k] *= al;
        }

        __syncthreads();   // everyone done reading Ks — reuse it for P
        #pragma unroll
        for (int i = 0; i < 4; i++)
            #pragma unroll
            for (int j = 0; j < 4; j++)
                Ks[((ty<<2)+i)*P + (tx<<2)+j] = s_[i][j];
        __syncthreads();

        // O += P @ V   (vv reads are 16B-aligned float4 -> LDS.128)
        #pragma unroll 8
        for (int j = 0; j < 64; j++) {
            float p[4];
            #pragma unroll
            for (int i = 0; i < 4; i++) p[i]  = Ks[((ty<<2)+i)*P + j];
            float4 vv = *reinterpret_cast<const float4*>(&Vs[j*P + (tx<<2)]);
            #pragma unroll
            for (int i = 0; i < 4; i++) {
                o[i][0] = fmaf(p[i], vv.x, o[i][0]);
                o[i][1] = fmaf(p[i], vv.y, o[i][1]);
                o[i][2] = fmaf(p[i], vv.z, o[i][2]);
                o[i][3] = fmaf(p[i], vv.w, o[i][3]);
            }
        }
    }

    // epilogue: normalize and write context in [b, t, H*HD] layout
    #pragma unroll
    for (int i = 0; i < 4; i++) {
        float rinv = 1.0f / l[i];
        int t = t0 + (ty<<2) + i;
        #pragma unroll
        for (int k = 0; k < 4; k++)
            ctx[(size_t)(b*T_ + t) * DIM_ + h*HD_ + (tx<<2)+k] = o[i][k] * rinv;
    }
}

// ---------------- launch ----------------
extern "C" void kernel_launch(void* const* d_in, const int* in_sizes, int n_in,
                              void* d_out, int out_size) {
    const float* hs = (const float*)d_in[0];
    const float* Wq = (const float*)d_in[1];
    const float* bq = (const float*)d_in[2];
    const float* Wk = (const float*)d_in[3];
    const float* bk = (const float*)d_in[4];
    const float* Wv = (const float*)d_in[5];
    const float* bv = (const float*)d_in[6];
    const float* Wo = (const float*)d_in[7];
    const float* bo = (const float*)d_in[8];
    float* out = (float*)d_out;

    float *q, *k, *v, *qr, *kr, *ctx;
    cudaGetSymbolAddress((void**)&q,   g_q);
    cudaGetSymbolAddress((void**)&k,   g_k);
    cudaGetSymbolAddress((void**)&v,   g_v);
    cudaGetSymbolAddress((void**)&qr,  g_qr);
    cudaGetSymbolAddress((void**)&kr,  g_kr);
    cudaGetSymbolAddress((void**)&ctx, g_ctx);

    // QKV projections
    sgemm_bias_kernel<<<dim3(DIM_/64, ROWS_/64), 256>>>(hs, Wq, bq, q, ROWS_, DIM_, DIM_);
    sgemm_bias_kernel<<<dim3(KVD_/64, ROWS_/64), 256>>>(hs, Wk, bk, k, ROWS_, KVD_, DIM_);
    sgemm_bias_kernel<<<dim3(KVD_/64, ROWS_/64), 256>>>(hs, Wv, bv, v, ROWS_, KVD_, DIM_);

    // RoPE on Q (wshift=10: width 1024) and K (wshift=8: width 256)
    rope_kernel<<<(ROWS_*DIM_ + 255)/256, 256>>>(q, qr, 10, ROWS_*DIM_);
    rope_kernel<<<(ROWS_*KVD_ + 255)/256, 256>>>(k, kr, 8, ROWS_*KVD_);

    // attention
    int smem = 3 * 64 * 68 * (int)sizeof(float);   // 52224 B
    cudaFuncSetAttribute(attn_kernel, cudaFuncAttributeMaxDynamicSharedMemorySize, smem);
    attn_kernel<<<dim3(T_/64, B_*H_), 256, smem>>>(qr, kr, v, ctx);

    // output projection
    sgemm_bias_kernel<<<dim3(DIM_/64, ROWS_/64), 256>>>(ctx, Wo, bo, out, ROWS_, DIM_, DIM_);
}

// round 15
// speedup vs baseline: 2.0295x; 1.5062x over previous
#include <cuda_runtime.h>
#include <math.h>

#define B_   2
#define T_   2048
#define DIM_ 1024
#define H_   16
#define HD_  64
#define G_   4
#define KVD_ 256          // (H_/G_) * HD_
#define ROWS_ (B_*T_)     // 4096

// ---------------- scratch (no cudaMalloc allowed) ----------------
__device__ float g_q  [ROWS_*DIM_];
__device__ float g_k  [ROWS_*KVD_];
__device__ float g_v  [ROWS_*KVD_];
__device__ float g_qr [ROWS_*DIM_];
__device__ float g_kr [ROWS_*KVD_];
__device__ float g_ctx[ROWS_*DIM_];

// ---------------- SGEMM: Y = X @ W^T + bias ----------------
// X[M,K] row-major, W[N,K] row-major, Y[M,N]. M%64==0, N%64==0, K%16==0.
// Transposed smem (k-major, stride 68): inner step = 2x LDS.128 + 16 FMA.
// Register-prefetched next k-slab.
__global__ __launch_bounds__(256) void sgemm_bias_kernel(
    const float* __restrict__ X, const float* __restrict__ W,
    const float* __restrict__ bias, float* __restrict__ Y,
    int M, int N, int K)
{
    const int S = 68;                      // row stride (floats), mult of 4
    __shared__ __align__(16) float Xs_t[16 * S];   // [kk][row]
    __shared__ __align__(16) float Ws_t[16 * S];   // [kk][col]

    int tid = threadIdx.x;
    int tx = tid & 15, ty = tid >> 4;
    int row0 = blockIdx.y << 6;
    int col0 = blockIdx.x << 6;

    // loader mapping: kidx = k within slab, rgrp*4..+3 = rows
    int kidx = tid & 15;
    int rgrp = tid >> 4;                   // 0..15

    const float* Xp = X + (size_t)(row0 + (rgrp << 2)) * K + kidx;
    const float* Wp = W + (size_t)(col0 + (rgrp << 2)) * K + kidx;

    float acc[4][4] = {};

    float xr[4], wr[4];
    #pragma unroll
    for (int rr = 0; rr < 4; rr++) {
        xr[rr] = Xp[(size_t)rr * K];
        wr[rr] = Wp[(size_t)rr * K];
    }

    for (int k0 = 0; k0 < K; k0 += 16) {
        #pragma unroll
        for (int rr = 0; rr < 4; rr++) {
            Xs_t[kidx * S + (rgrp << 2) + rr] = xr[rr];
            Ws_t[kidx * S + (rgrp << 2) + rr] = wr[rr];
        }
        __syncthreads();

        if (k0 + 16 < K) {
            #pragma unroll
            for (int rr = 0; rr < 4; rr++) {
                xr[rr] = Xp[(size_t)rr * K + k0 + 16];
                wr[rr] = Wp[(size_t)rr * K + k0 + 16];
            }
        }

        #pragma unroll
        for (int kk = 0; kk < 16; kk++) {
            float4 a4 = *reinterpret_cast<const float4*>(&Xs_t[kk * S + (ty << 2)]);
            float4 b4 = *reinterpret_cast<const float4*>(&Ws_t[kk * S + (tx << 2)]);
            float av[4] = {a4.x, a4.y, a4.z, a4.w};
            float bv[4] = {b4.x, b4.y, b4.z, b4.w};
            #pragma unroll
            for (int i = 0; i < 4; i++)
                #pragma unroll
                for (int j = 0; j < 4; j++)
                    acc[i][j] = fmaf(av[i], bv[j], acc[i][j]);
        }
        __syncthreads();
    }

    #pragma unroll
    for (int i = 0; i < 4; i++) {
        int r = row0 + (ty << 2) + i;
        #pragma unroll
        for (int j = 0; j < 4; j++) {
            int c = col0 + (tx << 2) + j;
            Y[(size_t)r * N + c] = acc[i][j] + bias[c];
        }
    }
}

// ---------------- RoPE (fp32 fast path) ----------------
__global__ __launch_bounds__(256) void rope_kernel(
    const float* __restrict__ in, float* __restrict__ out,
    int wshift, int total)
{
    int idx = blockIdx.x * blockDim.x + threadIdx.x;
    if (idx >= total) return;
    int d   = idx & 63;
    int row = idx >> wshift;        // b*T + t
    int t   = row & (T_ - 1);
    int j   = d & 31;

    const float neg_l2_over_32 = -0.4152410118609203f;   // -log2(10000)/32
    float inv = exp2f((float)j * neg_l2_over_32);
    float s, c;
    sincosf((float)t * inv, &s, &c);

    int hb = idx - d;
    float x = in[idx];
    float r = (d < 32) ? -in[hb + 2*d + 1] : in[hb + 2*(d - 32)];
    out[idx] = x * c + r * s;
}

// ---------------- Flash attention (fp32, full softmax) ----------------
// grid: (T/64 query tiles, B*H). block: 256 threads (16x16), 4x4 microtile.
// smem: Qs[64][68] row-major (q-row, d)
//       Kt[64][68] d-major  (d, k-row)  -- reused as P (q-row, s-col) row-major
//       Vs[64][68] row-major (k-row, d)
// d-major K makes the S-loop key read a stride-4 LDS.128 (2-way max) instead
// of the old stride-272 scalar reads (8-way conflicts).
__global__ __launch_bounds__(256) void attn_kernel(
    const float* __restrict__ Q, const float* __restrict__ K,
    const float* __restrict__ V, float* __restrict__ ctx)
{
    extern __shared__ float sm[];
    const int P = 68;
    float* Qs = sm;
    float* Kt = sm + 64 * P;      // also P buffer
    float* Vs = sm + 2 * 64 * P;

    int tid = threadIdx.x;
    int tx = tid & 15, ty = tid >> 4;
    int qt = blockIdx.x;
    int bh = blockIdx.y;
    int b = bh >> 4, h = bh & 15, kvh = h >> 2;
    int t0 = qt << 6;

    int lrow = tid >> 4;            // 0..15
    int lc   = (tid & 15) << 2;     // 0..60

    // K/V loader mapping: lane -> one d column, 16 rows
    int dcol = tid & 63;
    int rgrp = tid >> 6;            // 0..3

    const float scale = 0.125f;     // 1/sqrt(64)

    // load Q tile row-major (scale folded in); reads in S-loop are broadcast
    #pragma unroll
    for (int it = 0; it < 4; it++) {
        int r = (it << 4) + lrow;
        float4 q4 = *reinterpret_cast<const float4*>(
            &Q[(size_t)(b*T_ + t0 + r) * DIM_ + h*HD_ + lc]);
        Qs[r*P + lc+0] = q4.x * scale;
        Qs[r*P + lc+1] = q4.y * scale;
        Qs[r*P + lc+2] = q4.z * scale;
        Qs[r*P + lc+3] = q4.w * scale;
    }

    float m[4], l[4], o[4][4];
    #pragma unroll
    for (int i = 0; i < 4; i++) {
        m[i] = -INFINITY; l[i] = 0.f;
        #pragma unroll
        for (int k = 0; k < 4; k++) o[i][k] = 0.f;
    }

    #pragma unroll 1
    for (int kt = 0; kt < T_/64; kt++) {
        int s0 = kt << 6;
        __syncthreads();   // previous PV done with Kt(P)/Vs; also orders Q writes
        {
            const float* Kp = &K[(size_t)(b*T_ + s0 + (rgrp<<4)) * KVD_ + kvh*HD_ + dcol];
            const float* Vp = &V[(size_t)(b*T_ + s0 + (rgrp<<4)) * KVD_ + kvh*HD_ + dcol];
            #pragma unroll
            for (int rr = 0; rr < 16; rr++) {
                int r = (rgrp << 4) + rr;
                Kt[dcol*P + r] = Kp[(size_t)rr * KVD_];   // d-major
                Vs[r*P + dcol] = Vp[(size_t)rr * KVD_];   // row-major
            }
        }
        __syncthreads();

        // S = (Q*scale) @ K^T : 4-wide k groups, LDS.128 both sides
        float s_[4][4] = {};
        #pragma unroll 4
        for (int kk0 = 0; kk0 < HD_; kk0 += 4) {
            float4 aq[4], bk[4];
            #pragma unroll
            for (int i = 0; i < 4; i++)
                aq[i] = *reinterpret_cast<const float4*>(&Qs[((ty<<2)+i)*P + kk0]);
            #pragma unroll
            for (int c = 0; c < 4; c++)
                bk[c] = *reinterpret_cast<const float4*>(&Kt[(kk0+c)*P + (tx<<2)]);
            #pragma unroll
            for (int i = 0; i < 4; i++) {
                float av[4] = {aq[i].x, aq[i].y, aq[i].z, aq[i].w};
                #pragma unroll
                for (int c = 0; c < 4; c++) {
                    s_[i][0] = fmaf(av[c], bk[c].x, s_[i][0]);
                    s_[i][1] = fmaf(av[c], bk[c].y, s_[i][1]);
                    s_[i][2] = fmaf(av[c], bk[c].z, s_[i][2]);
                    s_[i][3] = fmaf(av[c], bk[c].w, s_[i][3]);
                }
            }
        }

        // online softmax update (rows shared by 16 lanes with the same ty)
        #pragma unroll
        for (int i = 0; i < 4; i++) {
            float mt = fmaxf(fmaxf(s_[i][0], s_[i][1]), fmaxf(s_[i][2], s_[i][3]));
            mt = fmaxf(mt, __shfl_xor_sync(0xffffffffu, mt, 1));
            mt = fmaxf(mt, __shfl_xor_sync(0xffffffffu, mt, 2));
            mt = fmaxf(mt, __shfl_xor_sync(0xffffffffu, mt, 4));
            mt = fmaxf(mt, __shfl_xor_sync(0xffffffffu, mt, 8));
            float mn = fmaxf(m[i], mt);
            float al = __expf(m[i] - mn);
            m[i] = mn;
            float rs = 0.f;
            #pragma unroll
            for (int j = 0; j < 4; j++) {
                float p = __expf(s_[i][j] - mn);
                s_[i][j] = p;
                rs += p;
            }
            rs += __shfl_xor_sync(0xffffffffu, rs, 1);
            rs += __shfl_xor_sync(0xffffffffu, rs, 2);
            rs += __shfl_xor_sync(0xffffffffu, rs, 4);
            rs += __shfl_xor_sync(0xffffffffu, rs, 8);
            l[i] = l[i] * al + rs;
            #pragma unroll
            for (int k = 0; k < 4; k++) o[i][k] *= al;
        }

        __syncthreads();   // all lanes done reading Kt — reuse it for P
        #pragma unroll
        for (int i = 0; i < 4; i++)
            #pragma unroll
            for (int j = 0; j < 4; j++)
                Kt[((ty<<2)+i)*P + (tx<<2)+j] = s_[i][j];
        __syncthreads();

        // O += P @ V : 4-wide j groups, LDS.128 both sides
        #pragma unroll 4
        for (int j0 = 0; j0 < 64; j0 += 4) {
            float4 pq[4], vv[4];
            #pragma unroll
            for (int i = 0; i < 4; i++)
                pq[i] = *reinterpret_cast<const float4*>(&Kt[((ty<<2)+i)*P + j0]);
            #pragma unroll
            for (int c = 0; c < 4; c++)
                vv[c] = *reinterpret_cast<const float4*>(&Vs[(j0+c)*P + (tx<<2)]);
            #pragma unroll
            for (int i = 0; i < 4; i++) {
                float pv[4] = {pq[i].x, pq[i].y, pq[i].z, pq[i].w};
                #pragma unroll
                for (int c = 0; c < 4; c++) {
                    o[i][0] = fmaf(pv[c], vv[c].x, o[i][0]);
                    o[i][1] = fmaf(pv[c], vv[c].y, o[i][1]);
                    o[i][2] = fmaf(pv[c], vv[c].z, o[i][2]);
                    o[i][3] = fmaf(pv[c], vv[c].w, o[i][3]);
                }
            }
        }
    }

    // epilogue: normalize and write context in [b, t, H*HD] layout
    #pragma unroll
    for (int i = 0; i < 4; i++) {
        float rinv = 1.0f / l[i];
        int t = t0 + (ty<<2) + i;
        #pragma unroll
        for (int k = 0; k < 4; k++)
            ctx[(size_t)(b*T_ + t) * DIM_ + h*HD_ + (tx<<2)+k] = o[i][k] * rinv;
    }
}

// ---------------- launch ----------------
extern "C" void kernel_launch(void* const* d_in, const int* in_sizes, int n_in,
                              void* d_out, int out_size) {
    const float* hs = (const float*)d_in[0];
    const float* Wq = (const float*)d_in[1];
    const float* bq = (const float*)d_in[2];
    const float* Wk = (const float*)d_in[3];
    const float* bk = (const float*)d_in[4];
    const float* Wv = (const float*)d_in[5];
    const float* bv = (const float*)d_in[6];
    const float* Wo = (const float*)d_in[7];
    const float* bo = (const float*)d_in[8];
    float* out = (float*)d_out;

    float *q, *k, *v, *qr, *kr, *ctx;
    cudaGetSymbolAddress((void**)&q,   g_q);
    cudaGetSymbolAddress((void**)&k,   g_k);
    cudaGetSymbolAddress((void**)&v,   g_v);
    cudaGetSymbolAddress((void**)&qr,  g_qr);
    cudaGetSymbolAddress((void**)&kr,  g_kr);
    cudaGetSymbolAddress((void**)&ctx, g_ctx);

    // QKV projections
    sgemm_bias_kernel<<<dim3(DIM_/64, ROWS_/64), 256>>>(hs, Wq, bq, q, ROWS_, DIM_, DIM_);
    sgemm_bias_kernel<<<dim3(KVD_/64, ROWS_/64), 256>>>(hs, Wk, bk, k, ROWS_, KVD_, DIM_);
    sgemm_bias_kernel<<<dim3(KVD_/64, ROWS_/64), 256>>>(hs, Wv, bv, v, ROWS_, KVD_, DIM_);

    // RoPE on Q (wshift=10: width 1024) and K (wshift=8: width 256)
    rope_kernel<<<(ROWS_*DIM_ + 255)/256, 256>>>(q, qr, 10, ROWS_*DIM_);
    rope_kernel<<<(ROWS_*KVD_ + 255)/256, 256>>>(k, kr, 8, ROWS_*KVD_);

    // attention
    int smem = 3 * 64 * 68 * (int)sizeof(float);   // 52224 B
    cudaFuncSetAttribute(attn_kernel, cudaFuncAttributeMaxDynamicSharedMemorySize, smem);
    attn_kernel<<<dim3(T_/64, B_*H_), 256, smem>>>(qr, kr, v, ctx);

    // output projection
    sgemm_bias_kernel<<<dim3(DIM_/64, ROWS_/64), 256>>>(ctx, Wo, bo, out, ROWS_, DIM_, DIM_);
}